// round 1
// baseline (speedup 1.0000x reference)
#include <cuda_runtime.h>

#define KIN 512
#define NH  128
#define N_MAX 100000

// ---------------- scratch (no allocations allowed) ----------------
__device__ float g_h   [(size_t)N_MAX * NH];   // h = x @ W
__device__ float g_agg1[(size_t)N_MAX * NH];   // clean aggregation
__device__ float g_agg2[(size_t)N_MAX * NH];   // corrupted aggregation
__device__ float g_norm_out[N_MAX];            // deg_out -> rsqrt
__device__ float g_norm_in [N_MAX];            // deg_in  -> rsqrt
__device__ float g_wsum[NH];                   // rowsum(mlp_W)
__device__ float g_bsum;                       // sum(mlp_b)

// ---------------- zero scratch ----------------
__global__ void zero_kernel(int N) {
    size_t idx    = (size_t)blockIdx.x * blockDim.x + threadIdx.x;
    size_t stride = (size_t)gridDim.x * blockDim.x;
    size_t n4 = (size_t)N * NH / 4;
    float4 z = make_float4(0.f, 0.f, 0.f, 0.f);
    float4* a1 = (float4*)g_agg1;
    float4* a2 = (float4*)g_agg2;
    for (size_t i = idx; i < n4; i += stride) { a1[i] = z; a2[i] = z; }
    for (size_t i = idx; i < (size_t)N; i += stride) {
        g_norm_out[i] = 0.f;
        g_norm_in[i]  = 0.f;
    }
}

// ---------------- degree counting ----------------
__global__ void degree_kernel(const int* __restrict__ src,
                              const int* __restrict__ dst, int E) {
    int i = blockIdx.x * blockDim.x + threadIdx.x;
    if (i < E) {
        atomicAdd(&g_norm_out[src[i]], 1.0f);
        atomicAdd(&g_norm_in [dst[i]], 1.0f);
    }
}

__global__ void norm_kernel(int N) {
    int i = blockIdx.x * blockDim.x + threadIdx.x;
    if (i < N) {
        g_norm_out[i] = rsqrtf(fmaxf(g_norm_out[i], 1.0f));
        g_norm_in[i]  = rsqrtf(fmaxf(g_norm_in[i],  1.0f));
    }
}

// ---------------- wsum = rowsum(mlp_W), bsum = sum(mlp_b) ----------------
__global__ void wsum_kernel(const float* __restrict__ mlpW,
                            const float* __restrict__ mlpb) {
    int j = threadIdx.x;   // 0..127
    float s = 0.f;
    #pragma unroll 8
    for (int k = 0; k < NH; k++) s += mlpW[j * NH + k];
    g_wsum[j] = s;
    __shared__ float sb[NH];
    sb[j] = mlpb[j];
    __syncthreads();
    if (j == 0) {
        float t = 0.f;
        for (int k = 0; k < NH; k++) t += sb[k];
        g_bsum = t;
    }
}

// ---------------- SGEMM: g_h[M,128] = x[M,512] @ W[512,128] ----------------
// 128x128 tile, BK=16, 256 threads, 8x8 per thread, fp32
#define BM 128
#define BN 128
#define BK 16
__global__ __launch_bounds__(256) void sgemm_kernel(
    const float* __restrict__ A,   // x
    const float* __restrict__ B,   // W
    int M) {
    __shared__ float As[BK][BM + 4];
    __shared__ float Bs[BK][BN];

    int tid = threadIdx.x;
    int tx = tid & 15;        // 0..15 -> N direction
    int ty = tid >> 4;        // 0..15 -> M direction
    int block_row = blockIdx.x * BM;

    float acc[8][8];
    #pragma unroll
    for (int i = 0; i < 8; i++)
        #pragma unroll
        for (int j = 0; j < 8; j++) acc[i][j] = 0.f;

    for (int k0 = 0; k0 < KIN; k0 += BK) {
        // load A tile (128 rows x 16 k), transposed into As[k][m]
        #pragma unroll
        for (int f = tid; f < BM * BK / 4; f += 256) {
            int r  = f >> 2;        // row within tile 0..127
            int c4 = f & 3;         // k-group 0..3
            int grow = block_row + r;
            float4 v = make_float4(0.f, 0.f, 0.f, 0.f);
            if (grow < M)
                v = *(const float4*)(A + (size_t)grow * KIN + k0 + c4 * 4);
            As[c4 * 4 + 0][r] = v.x;
            As[c4 * 4 + 1][r] = v.y;
            As[c4 * 4 + 2][r] = v.z;
            As[c4 * 4 + 3][r] = v.w;
        }
        // load B tile (16 k x 128 n)
        #pragma unroll
        for (int f = tid; f < BK * BN / 4; f += 256) {
            int r  = f >> 5;        // k 0..15
            int c4 = f & 31;        // n-group
            *(float4*)(&Bs[r][c4 * 4]) =
                *(const float4*)(B + (size_t)(k0 + r) * NH + c4 * 4);
        }
        __syncthreads();

        #pragma unroll
        for (int k = 0; k < BK; k++) {
            float a[8], bb[8];
            *(float4*)(a)      = *(const float4*)(&As[k][ty * 8]);
            *(float4*)(a + 4)  = *(const float4*)(&As[k][ty * 8 + 4]);
            *(float4*)(bb)     = *(const float4*)(&Bs[k][tx * 8]);
            *(float4*)(bb + 4) = *(const float4*)(&Bs[k][tx * 8 + 4]);
            #pragma unroll
            for (int i = 0; i < 8; i++)
                #pragma unroll
                for (int j = 0; j < 8; j++)
                    acc[i][j] = fmaf(a[i], bb[j], acc[i][j]);
        }
        __syncthreads();
    }

    #pragma unroll
    for (int i = 0; i < 8; i++) {
        int grow = block_row + ty * 8 + i;
        if (grow < M) {
            #pragma unroll
            for (int j = 0; j < 8; j += 4) {
                float4 v = make_float4(acc[i][j], acc[i][j + 1],
                                       acc[i][j + 2], acc[i][j + 3]);
                *(float4*)(g_h + (size_t)grow * NH + tx * 8 + j) = v;
            }
        }
    }
}

// ---------------- edge scatter: one warp per edge ----------------
__global__ void scatter_kernel(const int* __restrict__ src,
                               const int* __restrict__ dst,
                               const int* __restrict__ perm, int E) {
    size_t gid = (size_t)blockIdx.x * blockDim.x + threadIdx.x;
    int warp = (int)(gid >> 5);
    int lane = (int)(gid & 31);
    if (warp >= E) return;

    int s  = __ldg(&src[warp]);
    int d  = __ldg(&dst[warp]);
    int sp = __ldg(&perm[s]);
    float sc = g_norm_out[s];

    float4 v1 = *(const float4*)(g_h + (size_t)s  * NH + lane * 4);
    float4 v2 = *(const float4*)(g_h + (size_t)sp * NH + lane * 4);

    float* a1 = g_agg1 + (size_t)d * NH + lane * 4;
    float* a2 = g_agg2 + (size_t)d * NH + lane * 4;
    atomicAdd(a1 + 0, v1.x * sc);
    atomicAdd(a1 + 1, v1.y * sc);
    atomicAdd(a1 + 2, v1.z * sc);
    atomicAdd(a1 + 3, v1.w * sc);
    atomicAdd(a2 + 0, v2.x * sc);
    atomicAdd(a2 + 1, v2.y * sc);
    atomicAdd(a2 + 2, v2.z * sc);
    atomicAdd(a2 + 3, v2.w * sc);
}

// ---------------- finalize: norm_in, bias, PReLU, dot with wsum ----------------
__global__ void finalize_kernel(const float* __restrict__ b,
                                const float* __restrict__ alpha,
                                float* __restrict__ out, int N) {
    size_t gid = (size_t)blockIdx.x * blockDim.x + threadIdx.x;
    int node = (int)(gid >> 5);
    int lane = (int)(gid & 31);
    if (node >= N) return;

    float nin = g_norm_in[node];
    float4 bb = *(const float4*)(b      + lane * 4);
    float4 al = *(const float4*)(alpha  + lane * 4);
    float4 ws = *(const float4*)(g_wsum + lane * 4);
    float4 a1 = *(const float4*)(g_agg1 + (size_t)node * NH + lane * 4);
    float4 a2 = *(const float4*)(g_agg2 + (size_t)node * NH + lane * 4);

    float acc1 = 0.f, acc2 = 0.f, v;
    v = a1.x * nin + bb.x; v = (v >= 0.f) ? v : al.x * v; acc1 += v * ws.x;
    v = a1.y * nin + bb.y; v = (v >= 0.f) ? v : al.y * v; acc1 += v * ws.y;
    v = a1.z * nin + bb.z; v = (v >= 0.f) ? v : al.z * v; acc1 += v * ws.z;
    v = a1.w * nin + bb.w; v = (v >= 0.f) ? v : al.w * v; acc1 += v * ws.w;
    v = a2.x * nin + bb.x; v = (v >= 0.f) ? v : al.x * v; acc2 += v * ws.x;
    v = a2.y * nin + bb.y; v = (v >= 0.f) ? v : al.y * v; acc2 += v * ws.y;
    v = a2.z * nin + bb.z; v = (v >= 0.f) ? v : al.z * v; acc2 += v * ws.z;
    v = a2.w * nin + bb.w; v = (v >= 0.f) ? v : al.w * v; acc2 += v * ws.w;

    #pragma unroll
    for (int o = 16; o > 0; o >>= 1) {
        acc1 += __shfl_xor_sync(0xFFFFFFFFu, acc1, o);
        acc2 += __shfl_xor_sync(0xFFFFFFFFu, acc2, o);
    }
    if (lane == 0) {
        float bs = g_bsum;
        out[node]     = acc1 + bs;
        out[N + node] = acc2 + bs;
    }
}

// ---------------- launch ----------------
extern "C" void kernel_launch(void* const* d_in, const int* in_sizes, int n_in,
                              void* d_out, int out_size) {
    const float* x     = (const float*)d_in[0];
    const int*   src   = (const int*)  d_in[1];
    const int*   dst   = (const int*)  d_in[2];
    const int*   perm  = (const int*)  d_in[3];
    const float* W     = (const float*)d_in[4];
    const float* b     = (const float*)d_in[5];
    const float* alpha = (const float*)d_in[6];
    const float* mlpW  = (const float*)d_in[7];
    const float* mlpb  = (const float*)d_in[8];
    float* out = (float*)d_out;

    int E = in_sizes[1];
    int N = in_sizes[3];
    if (N > N_MAX) return;

    zero_kernel<<<2048, 256>>>(N);
    degree_kernel<<<(E + 255) / 256, 256>>>(src, dst, E);
    norm_kernel<<<(N + 255) / 256, 256>>>(N);
    wsum_kernel<<<1, NH>>>(mlpW, mlpb);
    sgemm_kernel<<<(N + BM - 1) / BM, 256>>>(x, W, N);

    size_t sthreads = (size_t)E * 32;
    scatter_kernel<<<(unsigned)((sthreads + 255) / 256), 256>>>(src, dst, perm, E);

    size_t fthreads = (size_t)N * 32;
    finalize_kernel<<<(unsigned)((fthreads + 255) / 256), 256>>>(b, alpha, out, N);
}

// round 2
// speedup vs baseline: 2.5442x; 2.5442x over previous
#include <cuda_runtime.h>

#define KIN 512
#define NH  128
#define N_MAX 100000
#define E_MAX 1600000
#define SCAN_B 256
#define NB_MAX ((N_MAX + SCAN_B - 1) / SCAN_B)

// ---------------- scratch (no allocations allowed) ----------------
__device__ float g_h[(size_t)N_MAX * NH];      // h = x @ W
__device__ int   g_deg_in [N_MAX];             // in-degree (int)
__device__ int   g_deg_out[N_MAX];             // out-degree (int)
__device__ float g_norm_out[N_MAX];
__device__ float g_norm_in [N_MAX];
__device__ int   g_row  [N_MAX];               // CSR row start (by dst)
__device__ int   g_cur  [N_MAX];               // fill cursor
__device__ int   g_csrc [E_MAX];               // CSR: src id per slot
__device__ int   g_part [NB_MAX];              // scan partials
__device__ int   g_poff [NB_MAX];              // scanned partials
__device__ float g_wsum[NH];                   // rowsum(mlp_W)
__device__ float g_bsum;                       // sum(mlp_b)

// ---------------- zero small scratch ----------------
__global__ void zero_kernel(int N) {
    int i = blockIdx.x * blockDim.x + threadIdx.x;
    if (i < N) { g_deg_in[i] = 0; g_deg_out[i] = 0; g_cur[i] = 0; }
}

// ---------------- degree counting (int) ----------------
__global__ void degree_kernel(const int* __restrict__ src,
                              const int* __restrict__ dst, int E) {
    int i = blockIdx.x * blockDim.x + threadIdx.x;
    if (i < E) {
        atomicAdd(&g_deg_out[src[i]], 1);
        atomicAdd(&g_deg_in [dst[i]], 1);
    }
}

__global__ void norm_kernel(int N) {
    int i = blockIdx.x * blockDim.x + threadIdx.x;
    if (i < N) {
        g_norm_out[i] = rsqrtf(fmaxf((float)g_deg_out[i], 1.0f));
        g_norm_in[i]  = rsqrtf(fmaxf((float)g_deg_in[i],  1.0f));
    }
}

// ---------------- 3-phase exclusive scan of g_deg_in -> g_row ----------------
__global__ void scan1_kernel(int N) {
    __shared__ int s[SCAN_B];
    int t = threadIdx.x;
    int i = blockIdx.x * SCAN_B + t;
    int v = (i < N) ? g_deg_in[i] : 0;
    s[t] = v;
    __syncthreads();
    int acc = v;
    #pragma unroll
    for (int o = 1; o < SCAN_B; o <<= 1) {
        int add = (t >= o) ? s[t - o] : 0;
        __syncthreads();
        acc += add;
        s[t] = acc;
        __syncthreads();
    }
    if (i < N) g_row[i] = acc - v;                 // exclusive within block
    if (t == SCAN_B - 1) g_part[blockIdx.x] = acc; // block total
}

__global__ void scan2_kernel(int nb) {
    __shared__ int s[512];
    int t = threadIdx.x;
    int v = (t < nb) ? g_part[t] : 0;
    s[t] = v;
    __syncthreads();
    int acc = v;
    #pragma unroll
    for (int o = 1; o < 512; o <<= 1) {
        int add = (t >= o) ? s[t - o] : 0;
        __syncthreads();
        acc += add;
        s[t] = acc;
        __syncthreads();
    }
    if (t < nb) g_poff[t] = acc - v;               // exclusive
}

__global__ void scan3_kernel(int N) {
    int i = blockIdx.x * SCAN_B + threadIdx.x;
    if (i < N) g_row[i] += g_poff[blockIdx.x];
}

// ---------------- CSR fill ----------------
__global__ void fill_kernel(const int* __restrict__ src,
                            const int* __restrict__ dst, int E) {
    int i = blockIdx.x * blockDim.x + threadIdx.x;
    if (i < E) {
        int d = dst[i];
        int pos = g_row[d] + atomicAdd(&g_cur[d], 1);
        g_csrc[pos] = src[i];
    }
}

// ---------------- wsum / bsum ----------------
__global__ void wsum_kernel(const float* __restrict__ mlpW) {
    int j = blockIdx.x;      // row 0..127
    int lane = threadIdx.x;  // 0..31
    float s = 0.f;
    #pragma unroll
    for (int k = lane; k < NH; k += 32) s += mlpW[j * NH + k];
    #pragma unroll
    for (int o = 16; o > 0; o >>= 1) s += __shfl_xor_sync(0xFFFFFFFFu, s, o);
    if (lane == 0) g_wsum[j] = s;
}

__global__ void bsum_kernel(const float* __restrict__ mlpb) {
    int lane = threadIdx.x;
    float s = 0.f;
    #pragma unroll
    for (int k = lane; k < NH; k += 32) s += mlpb[k];
    #pragma unroll
    for (int o = 16; o > 0; o >>= 1) s += __shfl_xor_sync(0xFFFFFFFFu, s, o);
    if (lane == 0) g_bsum = s;
}

// ---------------- SGEMM: g_h[M,128] = x[M,512] @ W[512,128] ----------------
#define BM 128
#define BN 128
#define BK 16
__global__ __launch_bounds__(256) void sgemm_kernel(
    const float* __restrict__ A,
    const float* __restrict__ B,
    int M) {
    __shared__ float As[BK][BM + 4];
    __shared__ float Bs[BK][BN];

    int tid = threadIdx.x;
    int tx = tid & 15;
    int ty = tid >> 4;
    int block_row = blockIdx.x * BM;

    float acc[8][8];
    #pragma unroll
    for (int i = 0; i < 8; i++)
        #pragma unroll
        for (int j = 0; j < 8; j++) acc[i][j] = 0.f;

    for (int k0 = 0; k0 < KIN; k0 += BK) {
        #pragma unroll
        for (int f = tid; f < BM * BK / 4; f += 256) {
            int r  = f >> 2;
            int c4 = f & 3;
            int grow = block_row + r;
            float4 v = make_float4(0.f, 0.f, 0.f, 0.f);
            if (grow < M)
                v = *(const float4*)(A + (size_t)grow * KIN + k0 + c4 * 4);
            As[c4 * 4 + 0][r] = v.x;
            As[c4 * 4 + 1][r] = v.y;
            As[c4 * 4 + 2][r] = v.z;
            As[c4 * 4 + 3][r] = v.w;
        }
        #pragma unroll
        for (int f = tid; f < BK * BN / 4; f += 256) {
            int r  = f >> 5;
            int c4 = f & 31;
            *(float4*)(&Bs[r][c4 * 4]) =
                *(const float4*)(B + (size_t)(k0 + r) * NH + c4 * 4);
        }
        __syncthreads();

        #pragma unroll
        for (int k = 0; k < BK; k++) {
            float a[8], bb[8];
            *(float4*)(a)      = *(const float4*)(&As[k][ty * 8]);
            *(float4*)(a + 4)  = *(const float4*)(&As[k][ty * 8 + 4]);
            *(float4*)(bb)     = *(const float4*)(&Bs[k][tx * 8]);
            *(float4*)(bb + 4) = *(const float4*)(&Bs[k][tx * 8 + 4]);
            #pragma unroll
            for (int i = 0; i < 8; i++)
                #pragma unroll
                for (int j = 0; j < 8; j++)
                    acc[i][j] = fmaf(a[i], bb[j], acc[i][j]);
        }
        __syncthreads();
    }

    #pragma unroll
    for (int i = 0; i < 8; i++) {
        int grow = block_row + ty * 8 + i;
        if (grow < M) {
            #pragma unroll
            for (int j = 0; j < 8; j += 4) {
                float4 v = make_float4(acc[i][j], acc[i][j + 1],
                                       acc[i][j + 2], acc[i][j + 3]);
                *(float4*)(g_h + (size_t)grow * NH + tx * 8 + j) = v;
            }
        }
    }
}

// ---------------- fused gather + finalize: one warp per dst node ----------------
__global__ void gather_kernel(const int* __restrict__ perm,
                              const float* __restrict__ b,
                              const float* __restrict__ alpha,
                              float* __restrict__ out, int N) {
    size_t gid = (size_t)blockIdx.x * blockDim.x + threadIdx.x;
    int node = (int)(gid >> 5);
    int lane = (int)(gid & 31);
    if (node >= N) return;

    int start = g_row[node];
    int cnt   = g_deg_in[node];

    float4 acc1 = make_float4(0.f, 0.f, 0.f, 0.f);
    float4 acc2 = make_float4(0.f, 0.f, 0.f, 0.f);

    for (int i = 0; i < cnt; i++) {
        int s  = __ldg(&g_csrc[start + i]);
        int sp = __ldg(&perm[s]);
        float sc = __ldg(&g_norm_out[s]);
        float4 v1 = *(const float4*)(g_h + (size_t)s  * NH + lane * 4);
        float4 v2 = *(const float4*)(g_h + (size_t)sp * NH + lane * 4);
        acc1.x = fmaf(v1.x, sc, acc1.x);
        acc1.y = fmaf(v1.y, sc, acc1.y);
        acc1.z = fmaf(v1.z, sc, acc1.z);
        acc1.w = fmaf(v1.w, sc, acc1.w);
        acc2.x = fmaf(v2.x, sc, acc2.x);
        acc2.y = fmaf(v2.y, sc, acc2.y);
        acc2.z = fmaf(v2.z, sc, acc2.z);
        acc2.w = fmaf(v2.w, sc, acc2.w);
    }

    float nin = g_norm_in[node];
    float4 bb = *(const float4*)(b      + lane * 4);
    float4 al = *(const float4*)(alpha  + lane * 4);
    float4 ws = *(const float4*)(g_wsum + lane * 4);

    float r1 = 0.f, r2 = 0.f, v;
    v = acc1.x * nin + bb.x; v = (v >= 0.f) ? v : al.x * v; r1 += v * ws.x;
    v = acc1.y * nin + bb.y; v = (v >= 0.f) ? v : al.y * v; r1 += v * ws.y;
    v = acc1.z * nin + bb.z; v = (v >= 0.f) ? v : al.z * v; r1 += v * ws.z;
    v = acc1.w * nin + bb.w; v = (v >= 0.f) ? v : al.w * v; r1 += v * ws.w;
    v = acc2.x * nin + bb.x; v = (v >= 0.f) ? v : al.x * v; r2 += v * ws.x;
    v = acc2.y * nin + bb.y; v = (v >= 0.f) ? v : al.y * v; r2 += v * ws.y;
    v = acc2.z * nin + bb.z; v = (v >= 0.f) ? v : al.z * v; r2 += v * ws.z;
    v = acc2.w * nin + bb.w; v = (v >= 0.f) ? v : al.w * v; r2 += v * ws.w;

    #pragma unroll
    for (int o = 16; o > 0; o >>= 1) {
        r1 += __shfl_xor_sync(0xFFFFFFFFu, r1, o);
        r2 += __shfl_xor_sync(0xFFFFFFFFu, r2, o);
    }
    if (lane == 0) {
        float bs = g_bsum;
        out[node]     = r1 + bs;
        out[N + node] = r2 + bs;
    }
}

// ---------------- launch ----------------
extern "C" void kernel_launch(void* const* d_in, const int* in_sizes, int n_in,
                              void* d_out, int out_size) {
    const float* x     = (const float*)d_in[0];
    const int*   src   = (const int*)  d_in[1];
    const int*   dst   = (const int*)  d_in[2];
    const int*   perm  = (const int*)  d_in[3];
    const float* W     = (const float*)d_in[4];
    const float* b     = (const float*)d_in[5];
    const float* alpha = (const float*)d_in[6];
    const float* mlpW  = (const float*)d_in[7];
    const float* mlpb  = (const float*)d_in[8];
    float* out = (float*)d_out;

    int E = in_sizes[1];
    int N = in_sizes[3];
    if (N > N_MAX || E > E_MAX) return;

    int nb = (N + SCAN_B - 1) / SCAN_B;

    zero_kernel  <<<(N + 255) / 256, 256>>>(N);
    degree_kernel<<<(E + 255) / 256, 256>>>(src, dst, E);
    norm_kernel  <<<(N + 255) / 256, 256>>>(N);
    scan1_kernel <<<nb, SCAN_B>>>(N);
    scan2_kernel <<<1, 512>>>(nb);
    scan3_kernel <<<nb, SCAN_B>>>(N);
    fill_kernel  <<<(E + 255) / 256, 256>>>(src, dst, E);
    wsum_kernel  <<<NH, 32>>>(mlpW);
    bsum_kernel  <<<1, 32>>>(mlpb);
    sgemm_kernel <<<(N + BM - 1) / BM, 256>>>(x, W, N);

    size_t gthreads = (size_t)N * 32;
    gather_kernel<<<(unsigned)((gthreads + 255) / 256), 256>>>(perm, b, alpha, out, N);
}

// round 4
// speedup vs baseline: 3.3629x; 1.3218x over previous
#include <cuda_runtime.h>
#include <cuda_bf16.h>
#include <cstdint>

#define KIN 512
#define NH  128
#define N_MAX 100000
#define E_MAX 1600000
#define SCAN_B 256
#define NB_MAX ((N_MAX + SCAN_B - 1) / SCAN_B)

// ---------------- scratch (no allocations allowed) ----------------
__device__ float g_h[(size_t)N_MAX * NH];      // h = x @ W
__device__ int   g_deg_in [N_MAX];
__device__ int   g_deg_out[N_MAX];
__device__ float g_norm_out[N_MAX];
__device__ float g_norm_in [N_MAX];
__device__ int   g_row  [N_MAX];
__device__ int   g_cur  [N_MAX];
__device__ int   g_csrc [E_MAX];
__device__ int   g_part [NB_MAX];
__device__ int   g_poff [NB_MAX];
__device__ float g_wsum[NH];
__device__ float g_bsum;
__device__ __nv_bfloat16 g_bhi[NH * KIN];      // W^T split-hi : [n][k]
__device__ __nv_bfloat16 g_blo[NH * KIN];      // W^T split-lo : [n][k]

// ================= helpers =================
__device__ __forceinline__ uint32_t smem_u32(const void* p) {
    uint32_t a;
    asm("{ .reg .u64 t; cvta.to.shared.u64 t, %1; cvt.u32.u64 %0, t; }"
        : "=r"(a) : "l"(p));
    return a;
}

__device__ __forceinline__ void ldsm4(uint32_t* r, uint32_t addr) {
    asm volatile("ldmatrix.sync.aligned.m8n8.x4.shared.b16 {%0,%1,%2,%3}, [%4];"
                 : "=r"(r[0]), "=r"(r[1]), "=r"(r[2]), "=r"(r[3]) : "r"(addr));
}

__device__ __forceinline__ void mma_bf16(float* d, const uint32_t* a, const uint32_t* b) {
    asm volatile(
        "mma.sync.aligned.m16n8k16.row.col.f32.bf16.bf16.f32 "
        "{%0,%1,%2,%3}, {%4,%5,%6,%7}, {%8,%9}, {%0,%1,%2,%3};"
        : "+f"(d[0]), "+f"(d[1]), "+f"(d[2]), "+f"(d[3])
        : "r"(a[0]), "r"(a[1]), "r"(a[2]), "r"(a[3]), "r"(b[0]), "r"(b[1]));
}

// ---------------- zero small scratch ----------------
__global__ void zero_kernel(int N) {
    int i = blockIdx.x * blockDim.x + threadIdx.x;
    if (i < N) { g_deg_in[i] = 0; g_deg_out[i] = 0; g_cur[i] = 0; }
}

// ---------------- degree counting ----------------
__global__ void degree_kernel(const int* __restrict__ src,
                              const int* __restrict__ dst, int E) {
    int i = blockIdx.x * blockDim.x + threadIdx.x;
    if (i < E) {
        atomicAdd(&g_deg_out[src[i]], 1);
        atomicAdd(&g_deg_in [dst[i]], 1);
    }
}

__global__ void norm_kernel(int N) {
    int i = blockIdx.x * blockDim.x + threadIdx.x;
    if (i < N) {
        g_norm_out[i] = rsqrtf(fmaxf((float)g_deg_out[i], 1.0f));
        g_norm_in[i]  = rsqrtf(fmaxf((float)g_deg_in[i],  1.0f));
    }
}

// ---------------- W transpose + bf16 split: g_bhi/g_blo[n][k] ----------------
__global__ void wsplit_kernel(const float* __restrict__ W) {
    int i = blockIdx.x * blockDim.x + threadIdx.x;  // over 512*128
    if (i < KIN * NH) {
        int k = i >> 7, n = i & 127;
        float v = W[i];
        __nv_bfloat16 h = __float2bfloat16(v);
        float l = v - __bfloat162float(h);
        g_bhi[n * KIN + k] = h;
        g_blo[n * KIN + k] = __float2bfloat16(l);
    }
}

// ---------------- scans ----------------
__global__ void scan1_kernel(int N) {
    __shared__ int s[SCAN_B];
    int t = threadIdx.x;
    int i = blockIdx.x * SCAN_B + t;
    int v = (i < N) ? g_deg_in[i] : 0;
    s[t] = v;
    __syncthreads();
    int acc = v;
    #pragma unroll
    for (int o = 1; o < SCAN_B; o <<= 1) {
        int add = (t >= o) ? s[t - o] : 0;
        __syncthreads();
        acc += add;
        s[t] = acc;
        __syncthreads();
    }
    if (i < N) g_row[i] = acc - v;
    if (t == SCAN_B - 1) g_part[blockIdx.x] = acc;
}

__global__ void scan2_kernel(int nb) {
    __shared__ int s[512];
    int t = threadIdx.x;
    int v = (t < nb) ? g_part[t] : 0;
    s[t] = v;
    __syncthreads();
    int acc = v;
    #pragma unroll
    for (int o = 1; o < 512; o <<= 1) {
        int add = (t >= o) ? s[t - o] : 0;
        __syncthreads();
        acc += add;
        s[t] = acc;
        __syncthreads();
    }
    if (t < nb) g_poff[t] = acc - v;
}

__global__ void scan3_kernel(int N) {
    int i = blockIdx.x * SCAN_B + threadIdx.x;
    if (i < N) g_row[i] += g_poff[blockIdx.x];
}

// ---------------- CSR fill ----------------
__global__ void fill_kernel(const int* __restrict__ src,
                            const int* __restrict__ dst, int E) {
    int i = blockIdx.x * blockDim.x + threadIdx.x;
    if (i < E) {
        int d = dst[i];
        int pos = g_row[d] + atomicAdd(&g_cur[d], 1);
        g_csrc[pos] = src[i];
    }
}

// ---------------- wsum / bsum ----------------
__global__ void wsum_kernel(const float* __restrict__ mlpW) {
    int j = blockIdx.x;
    int lane = threadIdx.x;
    float s = 0.f;
    #pragma unroll
    for (int k = lane; k < NH; k += 32) s += mlpW[j * NH + k];
    #pragma unroll
    for (int o = 16; o > 0; o >>= 1) s += __shfl_xor_sync(0xFFFFFFFFu, s, o);
    if (lane == 0) g_wsum[j] = s;
}

__global__ void bsum_kernel(const float* __restrict__ mlpb) {
    int lane = threadIdx.x;
    float s = 0.f;
    #pragma unroll
    for (int k = lane; k < NH; k += 32) s += mlpb[k];
    #pragma unroll
    for (int o = 16; o > 0; o >>= 1) s += __shfl_xor_sync(0xFFFFFFFFu, s, o);
    if (lane == 0) g_bsum = s;
}

// ============ split-bf16 HMMA GEMM: g_h[M,128] = x[M,512] @ W ============
// CTA: 128x128 tile, K-step 32, 8 warps (4m x 2n), warp tile 32x64.
// acc = Ahi*Bhi + Ahi*Blo + Alo*Bhi  (drop lo*lo term, ~2^-16)
#define PAD 40   // bf16 elems per SMEM row (80B -> conflict-free ldmatrix)

__global__ __launch_bounds__(256) void gemm_mma_kernel(const float* __restrict__ A, int M) {
    __shared__ __nv_bfloat16 sAhi[128 * PAD];
    __shared__ __nv_bfloat16 sAlo[128 * PAD];
    __shared__ __nv_bfloat16 sBhi[128 * PAD];
    __shared__ __nv_bfloat16 sBlo[128 * PAD];

    int tid = threadIdx.x;
    int lane = tid & 31, wid = tid >> 5;
    int wm = wid & 3;       // 0..3 : 32-row slab
    int wn = wid >> 2;      // 0..1 : 64-col slab
    int row0 = blockIdx.x * 128;

    float acc[2][8][4];
    #pragma unroll
    for (int i = 0; i < 2; i++)
        #pragma unroll
        for (int j = 0; j < 8; j++)
            #pragma unroll
            for (int q = 0; q < 4; q++) acc[i][j][q] = 0.f;

    // loader mapping: thread -> (row lr, k-half lh of 16)
    int lr = tid & 127;
    int lh = tid >> 7;
    bool avalid = (row0 + lr) < M;
    const float* aptr = A + (size_t)(row0 + lr) * KIN + lh * 16;
    const __nv_bfloat16* bhp = g_bhi + (size_t)lr * KIN + lh * 16;
    const __nv_bfloat16* blp = g_blo + (size_t)lr * KIN + lh * 16;
    int sidx = lr * PAD + lh * 16;   // SMEM element index for this loader

    uint32_t uAhi = smem_u32(sAhi), uAlo = smem_u32(sAlo);
    uint32_t uBhi = smem_u32(sBhi), uBlo = smem_u32(sBlo);
    uint32_t dAlo = uAlo - uAhi;
    uint32_t dBlo = uBlo - uBhi;

    #pragma unroll 1
    for (int t = 0; t < KIN / 32; t++) {
        int k0 = t * 32;

        float4 f0, f1, f2, f3;
        if (avalid) {
            const float4* p = (const float4*)(aptr + k0);
            f0 = p[0]; f1 = p[1]; f2 = p[2]; f3 = p[3];
        } else {
            f0 = make_float4(0.f, 0.f, 0.f, 0.f);
            f1 = f0; f2 = f0; f3 = f0;
        }
        uint4 vh0 = *(const uint4*)(bhp + k0);
        uint4 vh1 = *(const uint4*)(bhp + k0 + 8);
        uint4 vl0 = *(const uint4*)(blp + k0);
        uint4 vl1 = *(const uint4*)(blp + k0 + 8);

        __syncthreads();   // previous iteration's compute finished

        // A: split fp32 -> bf16 hi/lo, store 8 pairs
        {
            float fv[16] = {f0.x, f0.y, f0.z, f0.w, f1.x, f1.y, f1.z, f1.w,
                            f2.x, f2.y, f2.z, f2.w, f3.x, f3.y, f3.z, f3.w};
            #pragma unroll
            for (int p = 0; p < 8; p++) {
                float a = fv[2 * p], b = fv[2 * p + 1];
                __nv_bfloat162 h2 = __floats2bfloat162_rn(a, b);
                float la = a - __bfloat162float(h2.x);
                float lb = b - __bfloat162float(h2.y);
                __nv_bfloat162 l2 = __floats2bfloat162_rn(la, lb);
                *(uint32_t*)&sAhi[sidx + 2 * p] = *(uint32_t*)&h2;
                *(uint32_t*)&sAlo[sidx + 2 * p] = *(uint32_t*)&l2;
            }
        }
        // B: copy pre-split bf16
        *(uint4*)&sBhi[sidx]     = vh0;
        *(uint4*)&sBhi[sidx + 8] = vh1;
        *(uint4*)&sBlo[sidx]     = vl0;
        *(uint4*)&sBlo[sidx + 8] = vl1;

        __syncthreads();

        #pragma unroll
        for (int kk = 0; kk < 2; kk++) {
            int kc = kk * 16 + ((lane >> 4) << 3);   // col incl. lane k-offset
            int arow = wm * 32 + (lane & 15);
            uint32_t ah[2][4], al[2][4];
            #pragma unroll
            for (int mi = 0; mi < 2; mi++) {
                uint32_t addr = uAhi + (uint32_t)((arow + mi * 16) * PAD + kc) * 2;
                ldsm4(ah[mi], addr);
                ldsm4(al[mi], addr + dAlo);
            }
            int brow = wn * 64 + (lane & 15);
            uint32_t bh[8][2], bl[8][2];
            #pragma unroll
            for (int np = 0; np < 4; np++) {
                uint32_t r[4];
                uint32_t addr = uBhi + (uint32_t)((brow + np * 16) * PAD + kc) * 2;
                ldsm4(r, addr);
                bh[2 * np][0] = r[0]; bh[2 * np][1] = r[2];
                bh[2 * np + 1][0] = r[1]; bh[2 * np + 1][1] = r[3];
                ldsm4(r, addr + dBlo);
                bl[2 * np][0] = r[0]; bl[2 * np][1] = r[2];
                bl[2 * np + 1][0] = r[1]; bl[2 * np + 1][1] = r[3];
            }
            #pragma unroll
            for (int mi = 0; mi < 2; mi++)
                #pragma unroll
                for (int ni = 0; ni < 8; ni++) {
                    mma_bf16(acc[mi][ni], ah[mi], bh[ni]);
                    mma_bf16(acc[mi][ni], ah[mi], bl[ni]);
                    mma_bf16(acc[mi][ni], al[mi], bh[ni]);
                }
        }
    }

    // epilogue: D frag (m16n8): c0,c1 at (row=lane/4, col=2*(lane%4)), c2,c3 row+8
    int r = lane >> 2, c = (lane & 3) * 2;
    #pragma unroll
    for (int mi = 0; mi < 2; mi++) {
        int m0 = row0 + wm * 32 + mi * 16 + r;
        #pragma unroll
        for (int ni = 0; ni < 8; ni++) {
            int n = wn * 64 + ni * 8 + c;
            if (m0 < M)
                *(float2*)&g_h[(size_t)m0 * NH + n] =
                    make_float2(acc[mi][ni][0], acc[mi][ni][1]);
            if (m0 + 8 < M)
                *(float2*)&g_h[(size_t)(m0 + 8) * NH + n] =
                    make_float2(acc[mi][ni][2], acc[mi][ni][3]);
        }
    }
}

// ---------------- fused gather + finalize: one warp per dst node ----------------
__global__ void gather_kernel(const int* __restrict__ perm,
                              const float* __restrict__ b,
                              const float* __restrict__ alpha,
                              float* __restrict__ out, int N) {
    size_t gid = (size_t)blockIdx.x * blockDim.x + threadIdx.x;
    int node = (int)(gid >> 5);
    int lane = (int)(gid & 31);
    if (node >= N) return;

    int start = g_row[node];
    int cnt   = g_deg_in[node];

    float4 acc1 = make_float4(0.f, 0.f, 0.f, 0.f);
    float4 acc2 = make_float4(0.f, 0.f, 0.f, 0.f);

    for (int i = 0; i < cnt; i++) {
        int s  = __ldg(&g_csrc[start + i]);
        int sp = __ldg(&perm[s]);
        float sc = __ldg(&g_norm_out[s]);
        float4 v1 = *(const float4*)(g_h + (size_t)s  * NH + lane * 4);
        float4 v2 = *(const float4*)(g_h + (size_t)sp * NH + lane * 4);
        acc1.x = fmaf(v1.x, sc, acc1.x);
        acc1.y = fmaf(v1.y, sc, acc1.y);
        acc1.z = fmaf(v1.z, sc, acc1.z);
        acc1.w = fmaf(v1.w, sc, acc1.w);
        acc2.x = fmaf(v2.x, sc, acc2.x);
        acc2.y = fmaf(v2.y, sc, acc2.y);
        acc2.z = fmaf(v2.z, sc, acc2.z);
        acc2.w = fmaf(v2.w, sc, acc2.w);
    }

    float nin = g_norm_in[node];
    float4 bb = *(const float4*)(b      + lane * 4);
    float4 al = *(const float4*)(alpha  + lane * 4);
    float4 ws = *(const float4*)(g_wsum + lane * 4);

    float r1 = 0.f, r2 = 0.f, v;
    v = acc1.x * nin + bb.x; v = (v >= 0.f) ? v : al.x * v; r1 += v * ws.x;
    v = acc1.y * nin + bb.y; v = (v >= 0.f) ? v : al.y * v; r1 += v * ws.y;
    v = acc1.z * nin + bb.z; v = (v >= 0.f) ? v : al.z * v; r1 += v * ws.z;
    v = acc1.w * nin + bb.w; v = (v >= 0.f) ? v : al.w * v; r1 += v * ws.w;
    v = acc2.x * nin + bb.x; v = (v >= 0.f) ? v : al.x * v; r2 += v * ws.x;
    v = acc2.y * nin + bb.y; v = (v >= 0.f) ? v : al.y * v; r2 += v * ws.y;
    v = acc2.z * nin + bb.z; v = (v >= 0.f) ? v : al.z * v; r2 += v * ws.z;
    v = acc2.w * nin + bb.w; v = (v >= 0.f) ? v : al.w * v; r2 += v * ws.w;

    #pragma unroll
    for (int o = 16; o > 0; o >>= 1) {
        r1 += __shfl_xor_sync(0xFFFFFFFFu, r1, o);
        r2 += __shfl_xor_sync(0xFFFFFFFFu, r2, o);
    }
    if (lane == 0) {
        float bs = g_bsum;
        out[node]     = r1 + bs;
        out[N + node] = r2 + bs;
    }
}

// ---------------- launch ----------------
extern "C" void kernel_launch(void* const* d_in, const int* in_sizes, int n_in,
                              void* d_out, int out_size) {
    const float* x     = (const float*)d_in[0];
    const int*   src   = (const int*)  d_in[1];
    const int*   dst   = (const int*)  d_in[2];
    const int*   perm  = (const int*)  d_in[3];
    const float* W     = (const float*)d_in[4];
    const float* b     = (const float*)d_in[5];
    const float* alpha = (const float*)d_in[6];
    const float* mlpW  = (const float*)d_in[7];
    const float* mlpb  = (const float*)d_in[8];
    float* out = (float*)d_out;

    int E = in_sizes[1];
    int N = in_sizes[3];
    if (N > N_MAX || E > E_MAX) return;

    int nb = (N + SCAN_B - 1) / SCAN_B;

    zero_kernel   <<<(N + 255) / 256, 256>>>(N);
    degree_kernel <<<(E + 255) / 256, 256>>>(src, dst, E);
    wsplit_kernel <<<(KIN * NH + 255) / 256, 256>>>(W);
    gemm_mma_kernel<<<(N + 127) / 128, 256>>>(x, N);   // launch index 3 (ncu target)
    norm_kernel   <<<(N + 255) / 256, 256>>>(N);
    scan1_kernel  <<<nb, SCAN_B>>>(N);
    scan2_kernel  <<<1, 512>>>(nb);
    scan3_kernel  <<<nb, SCAN_B>>>(N);
    fill_kernel   <<<(E + 255) / 256, 256>>>(src, dst, E);
    wsum_kernel   <<<NH, 32>>>(mlpW);
    bsum_kernel   <<<1, 32>>>(mlpb);

    size_t gthreads = (size_t)N * 32;
    gather_kernel<<<(unsigned)((gthreads + 255) / 256), 256>>>(perm, b, alpha, out, N);
}

// round 5
// speedup vs baseline: 3.7487x; 1.1147x over previous
#include <cuda_runtime.h>
#include <cuda_bf16.h>
#include <cstdint>

#define KIN 512
#define NH  128
#define N_MAX 100000
#define E_MAX 1600000
#define SCAN_B 256
#define NB_MAX ((N_MAX + SCAN_B - 1) / SCAN_B)

// ---------------- scratch (no allocations allowed) ----------------
__device__ float g_h[(size_t)N_MAX * NH];      // h = x @ W
__device__ int   g_deg_in [N_MAX];
__device__ int   g_deg_out[N_MAX];
__device__ float g_norm_out[N_MAX];
__device__ float g_norm_in [N_MAX];
__device__ int   g_row  [N_MAX];
__device__ int   g_cur  [N_MAX];
__device__ int   g_csrc [E_MAX];
__device__ int   g_part [NB_MAX];
__device__ int   g_poff [NB_MAX];
__device__ float g_wsum[NH];
__device__ float g_bsum;
__device__ __nv_bfloat16 g_bhi[NH * KIN];      // W^T split-hi : [n][k]
__device__ __nv_bfloat16 g_blo[NH * KIN];      // W^T split-lo : [n][k]

// ================= helpers =================
__device__ __forceinline__ uint32_t smem_u32(const void* p) {
    uint32_t a;
    asm("{ .reg .u64 t; cvta.to.shared.u64 t, %1; cvt.u32.u64 %0, t; }"
        : "=r"(a) : "l"(p));
    return a;
}

__device__ __forceinline__ void ldsm4(uint32_t* r, uint32_t addr) {
    asm volatile("ldmatrix.sync.aligned.m8n8.x4.shared.b16 {%0,%1,%2,%3}, [%4];"
                 : "=r"(r[0]), "=r"(r[1]), "=r"(r[2]), "=r"(r[3]) : "r"(addr));
}

__device__ __forceinline__ void mma_bf16(float* d, const uint32_t* a, const uint32_t* b) {
    asm volatile(
        "mma.sync.aligned.m16n8k16.row.col.f32.bf16.bf16.f32 "
        "{%0,%1,%2,%3}, {%4,%5,%6,%7}, {%8,%9}, {%0,%1,%2,%3};"
        : "+f"(d[0]), "+f"(d[1]), "+f"(d[2]), "+f"(d[3])
        : "r"(a[0]), "r"(a[1]), "r"(a[2]), "r"(a[3]), "r"(b[0]), "r"(b[1]));
}

#define CP16(dst, src) \
    asm volatile("cp.async.cg.shared.global [%0], [%1], 16;" :: "r"(dst), "l"(src))
#define CP_COMMIT() asm volatile("cp.async.commit_group;" ::: "memory")
#define CP_WAIT0()  asm volatile("cp.async.wait_group 0;"  ::: "memory")
#define STS128(a, r0, r1, r2, r3) \
    asm volatile("st.shared.v4.b32 [%0], {%1,%2,%3,%4};" \
                 :: "r"(a), "r"(r0), "r"(r1), "r"(r2), "r"(r3))

// ---------------- zero small scratch ----------------
__global__ void zero_kernel(int N) {
    int i = blockIdx.x * blockDim.x + threadIdx.x;
    if (i < N) { g_deg_in[i] = 0; g_deg_out[i] = 0; g_cur[i] = 0; }
}

// ---------------- degree counting ----------------
__global__ void degree_kernel(const int* __restrict__ src,
                              const int* __restrict__ dst, int E) {
    int i = blockIdx.x * blockDim.x + threadIdx.x;
    if (i < E) {
        atomicAdd(&g_deg_out[src[i]], 1);
        atomicAdd(&g_deg_in [dst[i]], 1);
    }
}

__global__ void norm_kernel(int N) {
    int i = blockIdx.x * blockDim.x + threadIdx.x;
    if (i < N) {
        g_norm_out[i] = rsqrtf(fmaxf((float)g_deg_out[i], 1.0f));
        g_norm_in[i]  = rsqrtf(fmaxf((float)g_deg_in[i],  1.0f));
    }
}

// ---------------- W transpose + bf16 split: g_bhi/g_blo[n][k] ----------------
__global__ void wsplit_kernel(const float* __restrict__ W) {
    int i = blockIdx.x * blockDim.x + threadIdx.x;
    if (i < KIN * NH) {
        int k = i >> 7, n = i & 127;
        float v = W[i];
        __nv_bfloat16 h = __float2bfloat16(v);
        float l = v - __bfloat162float(h);
        g_bhi[n * KIN + k] = h;
        g_blo[n * KIN + k] = __float2bfloat16(l);
    }
}

// ---------------- scans ----------------
__global__ void scan1_kernel(int N) {
    __shared__ int s[SCAN_B];
    int t = threadIdx.x;
    int i = blockIdx.x * SCAN_B + t;
    int v = (i < N) ? g_deg_in[i] : 0;
    s[t] = v;
    __syncthreads();
    int acc = v;
    #pragma unroll
    for (int o = 1; o < SCAN_B; o <<= 1) {
        int add = (t >= o) ? s[t - o] : 0;
        __syncthreads();
        acc += add;
        s[t] = acc;
        __syncthreads();
    }
    if (i < N) g_row[i] = acc - v;
    if (t == SCAN_B - 1) g_part[blockIdx.x] = acc;
}

__global__ void scan2_kernel(int nb) {
    __shared__ int s[512];
    int t = threadIdx.x;
    int v = (t < nb) ? g_part[t] : 0;
    s[t] = v;
    __syncthreads();
    int acc = v;
    #pragma unroll
    for (int o = 1; o < 512; o <<= 1) {
        int add = (t >= o) ? s[t - o] : 0;
        __syncthreads();
        acc += add;
        s[t] = acc;
        __syncthreads();
    }
    if (t < nb) g_poff[t] = acc - v;
}

__global__ void scan3_kernel(int N) {
    int i = blockIdx.x * SCAN_B + threadIdx.x;
    if (i < N) g_row[i] += g_poff[blockIdx.x];
}

// ---------------- CSR fill ----------------
__global__ void fill_kernel(const int* __restrict__ src,
                            const int* __restrict__ dst, int E) {
    int i = blockIdx.x * blockDim.x + threadIdx.x;
    if (i < E) {
        int d = dst[i];
        int pos = g_row[d] + atomicAdd(&g_cur[d], 1);
        g_csrc[pos] = src[i];
    }
}

// ---------------- wsum / bsum ----------------
__global__ void wsum_kernel(const float* __restrict__ mlpW) {
    int j = blockIdx.x;
    int lane = threadIdx.x;
    float s = 0.f;
    #pragma unroll
    for (int k = lane; k < NH; k += 32) s += mlpW[j * NH + k];
    #pragma unroll
    for (int o = 16; o > 0; o >>= 1) s += __shfl_xor_sync(0xFFFFFFFFu, s, o);
    if (lane == 0) g_wsum[j] = s;
}

__global__ void bsum_kernel(const float* __restrict__ mlpb) {
    int lane = threadIdx.x;
    float s = 0.f;
    #pragma unroll
    for (int k = lane; k < NH; k += 32) s += mlpb[k];
    #pragma unroll
    for (int o = 16; o > 0; o >>= 1) s += __shfl_xor_sync(0xFFFFFFFFu, s, o);
    if (lane == 0) g_bsum = s;
}

// ============ split-bf16 HMMA GEMM, double-buffered + cp.async ============
// CTA: 128x128 tile, K-step 32, 8 warps (4m x 2n), warp tile 32x64.
// acc = Ahi*Bhi + Ahi*Blo + Alo*Bhi  (drop lo*lo)
#define PAD 40           // bf16 elems per SMEM row (80B)
#define STAGE_B 40960    // 4 arrays x 128*PAD*2B
#define OFF_ALO 10240
#define OFF_BHI 20480
#define OFF_BLO 30720
#define GEMM_SMEM (2 * STAGE_B)
#define NKT (KIN / 32)   // 16 K-tiles

__global__ __launch_bounds__(256) void gemm_mma_kernel(const float* __restrict__ A, int M) {
    extern __shared__ char smem[];
    uint32_t sb = smem_u32(smem);

    int tid = threadIdx.x;
    int lane = tid & 31, wid = tid >> 5;
    int wm = wid & 3;       // 32-row slab
    int wn = wid >> 2;      // 64-col slab
    int row0 = blockIdx.x * 128;

    float acc[2][8][4];
    #pragma unroll
    for (int i = 0; i < 2; i++)
        #pragma unroll
        for (int j = 0; j < 8; j++)
            #pragma unroll
            for (int q = 0; q < 4; q++) acc[i][j][q] = 0.f;

    // loader mapping
    int lr = tid & 127;          // row within tile
    int lh = tid >> 7;           // k-half (16 floats each)
    bool avalid = (row0 + lr) < M;
    const float* aptr = A + (size_t)(row0 + lr) * KIN + lh * 16;
    int br0 = tid >> 2;          // B row for chunk 0 (0..63)
    int bpart = (tid & 3) * 16;  // 16B part within 64B row

    float fA[16];
    // ---- prologue: A(0) regs + B(0) cp.async ----
    if (avalid) {
        const float4* p = (const float4*)aptr;
        *(float4*)(fA)      = p[0];
        *(float4*)(fA + 4)  = p[1];
        *(float4*)(fA + 8)  = p[2];
        *(float4*)(fA + 12) = p[3];
    } else {
        #pragma unroll
        for (int i = 0; i < 16; i++) fA[i] = 0.f;
    }
    #pragma unroll
    for (int i = 0; i < 2; i++) {
        int r = br0 + i * 64;
        uint32_t d = sb + OFF_BHI + (uint32_t)r * 80 + bpart;
        CP16(d, (const char*)(g_bhi + (size_t)r * KIN) + bpart);
        CP16(d + (OFF_BLO - OFF_BHI), (const char*)(g_blo + (size_t)r * KIN) + bpart);
    }
    CP_COMMIT();

    #pragma unroll 1
    for (int t = 0; t < NKT; t++) {
        uint32_t base = sb + (uint32_t)(t & 1) * STAGE_B;

        // ---- convert & store A(t) (packed 16B stores) ----
        uint32_t hi[8], lo[8];
        #pragma unroll
        for (int p = 0; p < 8; p++) {
            float a = fA[2 * p], b = fA[2 * p + 1];
            __nv_bfloat162 h2 = __floats2bfloat162_rn(a, b);
            float la = a - __bfloat162float(h2.x);
            float lb = b - __bfloat162float(h2.y);
            __nv_bfloat162 l2 = __floats2bfloat162_rn(la, lb);
            hi[p] = *(uint32_t*)&h2;
            lo[p] = *(uint32_t*)&l2;
        }
        uint32_t adst = base + (uint32_t)lr * 80 + (uint32_t)lh * 32;
        STS128(adst,      hi[0], hi[1], hi[2], hi[3]);
        STS128(adst + 16, hi[4], hi[5], hi[6], hi[7]);
        STS128(adst + OFF_ALO,      lo[0], lo[1], lo[2], lo[3]);
        STS128(adst + OFF_ALO + 16, lo[4], lo[5], lo[6], lo[7]);

        CP_WAIT0();
        __syncthreads();

        // ---- prefetch stage t+1 ----
        if (t + 1 < NKT) {
            int k0n = (t + 1) * 32;
            if (avalid) {
                const float4* p = (const float4*)(aptr + k0n);
                *(float4*)(fA)      = p[0];
                *(float4*)(fA + 4)  = p[1];
                *(float4*)(fA + 8)  = p[2];
                *(float4*)(fA + 12) = p[3];
            }
            uint32_t nbase = sb + (uint32_t)((t + 1) & 1) * STAGE_B;
            #pragma unroll
            for (int i = 0; i < 2; i++) {
                int r = br0 + i * 64;
                uint32_t d = nbase + OFF_BHI + (uint32_t)r * 80 + bpart;
                CP16(d, (const char*)(g_bhi + (size_t)r * KIN + k0n) + bpart);
                CP16(d + (OFF_BLO - OFF_BHI),
                     (const char*)(g_blo + (size_t)r * KIN + k0n) + bpart);
            }
            CP_COMMIT();
        }

        // ---- compute stage t ----
        uint32_t uAhi = base, uAlo = base + OFF_ALO;
        uint32_t uBhi = base + OFF_BHI, uBlo = base + OFF_BLO;
        #pragma unroll
        for (int kk = 0; kk < 2; kk++) {
            int kc = kk * 16 + ((lane >> 4) << 3);
            int arow = wm * 32 + (lane & 15);
            uint32_t ah[2][4], al[2][4];
            #pragma unroll
            for (int mi = 0; mi < 2; mi++) {
                uint32_t addr = uAhi + (uint32_t)((arow + mi * 16) * PAD + kc) * 2;
                ldsm4(ah[mi], addr);
                ldsm4(al[mi], addr + OFF_ALO);
            }
            int brow = wn * 64 + (lane & 15);
            uint32_t bh[8][2], bl[8][2];
            #pragma unroll
            for (int np = 0; np < 4; np++) {
                uint32_t r[4];
                uint32_t addr = uBhi + (uint32_t)((brow + np * 16) * PAD + kc) * 2;
                ldsm4(r, addr);
                bh[2 * np][0] = r[0]; bh[2 * np][1] = r[2];
                bh[2 * np + 1][0] = r[1]; bh[2 * np + 1][1] = r[3];
                ldsm4(r, addr + (OFF_BLO - OFF_BHI));
                bl[2 * np][0] = r[0]; bl[2 * np][1] = r[2];
                bl[2 * np + 1][0] = r[1]; bl[2 * np + 1][1] = r[3];
            }
            #pragma unroll
            for (int mi = 0; mi < 2; mi++)
                #pragma unroll
                for (int ni = 0; ni < 8; ni++) {
                    mma_bf16(acc[mi][ni], ah[mi], bh[ni]);
                    mma_bf16(acc[mi][ni], ah[mi], bl[ni]);
                    mma_bf16(acc[mi][ni], al[mi], bh[ni]);
                }
        }
    }

    // ---- epilogue ----
    int r = lane >> 2, c = (lane & 3) * 2;
    #pragma unroll
    for (int mi = 0; mi < 2; mi++) {
        int m0 = row0 + wm * 32 + mi * 16 + r;
        #pragma unroll
        for (int ni = 0; ni < 8; ni++) {
            int n = wn * 64 + ni * 8 + c;
            if (m0 < M)
                *(float2*)&g_h[(size_t)m0 * NH + n] =
                    make_float2(acc[mi][ni][0], acc[mi][ni][1]);
            if (m0 + 8 < M)
                *(float2*)&g_h[(size_t)(m0 + 8) * NH + n] =
                    make_float2(acc[mi][ni][2], acc[mi][ni][3]);
        }
    }
}

// ---------------- fused gather + finalize: one warp per dst node ----------------
__global__ void gather_kernel(const int* __restrict__ perm,
                              const float* __restrict__ b,
                              const float* __restrict__ alpha,
                              float* __restrict__ out, int N) {
    size_t gid = (size_t)blockIdx.x * blockDim.x + threadIdx.x;
    int node = (int)(gid >> 5);
    int lane = (int)(gid & 31);
    if (node >= N) return;

    int start = g_row[node];
    int cnt   = g_deg_in[node];

    float4 acc1 = make_float4(0.f, 0.f, 0.f, 0.f);
    float4 acc2 = make_float4(0.f, 0.f, 0.f, 0.f);

    for (int i = 0; i < cnt; i++) {
        int s  = __ldg(&g_csrc[start + i]);
        int sp = __ldg(&perm[s]);
        float sc = __ldg(&g_norm_out[s]);
        float4 v1 = *(const float4*)(g_h + (size_t)s  * NH + lane * 4);
        float4 v2 = *(const float4*)(g_h + (size_t)sp * NH + lane * 4);
        acc1.x = fmaf(v1.x, sc, acc1.x);
        acc1.y = fmaf(v1.y, sc, acc1.y);
        acc1.z = fmaf(v1.z, sc, acc1.z);
        acc1.w = fmaf(v1.w, sc, acc1.w);
        acc2.x = fmaf(v2.x, sc, acc2.x);
        acc2.y = fmaf(v2.y, sc, acc2.y);
        acc2.z = fmaf(v2.z, sc, acc2.z);
        acc2.w = fmaf(v2.w, sc, acc2.w);
    }

    float nin = g_norm_in[node];
    float4 bb = *(const float4*)(b      + lane * 4);
    float4 al = *(const float4*)(alpha  + lane * 4);
    float4 ws = *(const float4*)(g_wsum + lane * 4);

    float r1 = 0.f, r2 = 0.f, v;
    v = acc1.x * nin + bb.x; v = (v >= 0.f) ? v : al.x * v; r1 += v * ws.x;
    v = acc1.y * nin + bb.y; v = (v >= 0.f) ? v : al.y * v; r1 += v * ws.y;
    v = acc1.z * nin + bb.z; v = (v >= 0.f) ? v : al.z * v; r1 += v * ws.z;
    v = acc1.w * nin + bb.w; v = (v >= 0.f) ? v : al.w * v; r1 += v * ws.w;
    v = acc2.x * nin + bb.x; v = (v >= 0.f) ? v : al.x * v; r2 += v * ws.x;
    v = acc2.y * nin + bb.y; v = (v >= 0.f) ? v : al.y * v; r2 += v * ws.y;
    v = acc2.z * nin + bb.z; v = (v >= 0.f) ? v : al.z * v; r2 += v * ws.z;
    v = acc2.w * nin + bb.w; v = (v >= 0.f) ? v : al.w * v; r2 += v * ws.w;

    #pragma unroll
    for (int o = 16; o > 0; o >>= 1) {
        r1 += __shfl_xor_sync(0xFFFFFFFFu, r1, o);
        r2 += __shfl_xor_sync(0xFFFFFFFFu, r2, o);
    }
    if (lane == 0) {
        float bs = g_bsum;
        out[node]     = r1 + bs;
        out[N + node] = r2 + bs;
    }
}

// ---------------- launch ----------------
extern "C" void kernel_launch(void* const* d_in, const int* in_sizes, int n_in,
                              void* d_out, int out_size) {
    const float* x     = (const float*)d_in[0];
    const int*   src   = (const int*)  d_in[1];
    const int*   dst   = (const int*)  d_in[2];
    const int*   perm  = (const int*)  d_in[3];
    const float* W     = (const float*)d_in[4];
    const float* b     = (const float*)d_in[5];
    const float* alpha = (const float*)d_in[6];
    const float* mlpW  = (const float*)d_in[7];
    const float* mlpb  = (const float*)d_in[8];
    float* out = (float*)d_out;

    int E = in_sizes[1];
    int N = in_sizes[3];
    if (N > N_MAX || E > E_MAX) return;

    int nb = (N + SCAN_B - 1) / SCAN_B;

    cudaFuncSetAttribute(gemm_mma_kernel,
                         cudaFuncAttributeMaxDynamicSharedMemorySize, GEMM_SMEM);

    zero_kernel   <<<(N + 255) / 256, 256>>>(N);
    degree_kernel <<<(E + 255) / 256, 256>>>(src, dst, E);
    wsplit_kernel <<<(KIN * NH + 255) / 256, 256>>>(W);
    gemm_mma_kernel<<<(N + 127) / 128, 256, GEMM_SMEM>>>(x, N);   // launch index 3 (ncu target)
    norm_kernel   <<<(N + 255) / 256, 256>>>(N);
    scan1_kernel  <<<nb, SCAN_B>>>(N);
    scan2_kernel  <<<1, 512>>>(nb);
    scan3_kernel  <<<nb, SCAN_B>>>(N);
    fill_kernel   <<<(E + 255) / 256, 256>>>(src, dst, E);
    wsum_kernel   <<<NH, 32>>>(mlpW);
    bsum_kernel   <<<1, 32>>>(mlpb);

    size_t gthreads = (size_t)N * 32;
    gather_kernel<<<(unsigned)((gthreads + 255) / 256), 256>>>(perm, b, alpha, out, N);
}